// round 7
// baseline (speedup 1.0000x reference)
#include <cuda_runtime.h>
#include <cuda_fp16.h>
#include <cstdint>

#define NNODES 4096
#define RREL   16
#define NBASES 8
#define DIN    64
#define DOUT   32
#define KFULL  (RREL * NNODES)          // 65536

#define M_TILE 128
#define KT     64                       // k per step (4 mma k-tiles of 16)
#define KSPLIT 32
#define KCHUNK (KFULL / KSPLIT)         // 2048
#define NSTEPS (KCHUNK / KT)            // 32

// per-stage smem layout (bytes): A 16K | B-hi 4K | B-lo 4K
#define OFF_AH 0
#define OFF_BH 16384
#define OFF_BL 20480
#define STG_B  24576
#define SMEM_BYTES (2 * STG_B)          // 48 KB dynamic

__device__ float g_W[RREL * DIN * DOUT];
__device__ __half g_Bh[(size_t)DOUT * KFULL];            // [c][k], 4 MB
__device__ __half g_Bl[(size_t)DOUT * KFULL];            // 4 MB
__device__ float g_part[(size_t)KSPLIT * NNODES * DOUT]; // 16 MB

__device__ __forceinline__ void mma16816(float* d, const uint32_t* a,
                                         uint32_t b0, uint32_t b1) {
    asm volatile(
        "mma.sync.aligned.m16n8k16.row.col.f32.f16.f16.f32 "
        "{%0,%1,%2,%3}, {%4,%5,%6,%7}, {%8,%9}, {%0,%1,%2,%3};"
        : "+f"(d[0]), "+f"(d[1]), "+f"(d[2]), "+f"(d[3])
        : "r"(a[0]), "r"(a[1]), "r"(a[2]), "r"(a[3]), "r"(b0), "r"(b1));
}
__device__ __forceinline__ void cp_async16(uint32_t saddr, const void* g) {
    asm volatile("cp.async.cg.shared.global [%0], [%1], 16;" :: "r"(saddr), "l"(g));
}
__device__ __forceinline__ void ldmatrix_x4(uint32_t* r, uint32_t addr) {
    asm volatile("ldmatrix.sync.aligned.m8n8.x4.shared.b16 {%0,%1,%2,%3}, [%4];"
                 : "=r"(r[0]), "=r"(r[1]), "=r"(r[2]), "=r"(r[3]) : "r"(addr));
}
__device__ __forceinline__ void ldmatrix_x2(uint32_t* r, uint32_t addr) {
    asm volatile("ldmatrix.sync.aligned.m8n8.x2.shared.b16 {%0,%1}, [%2];"
                 : "=r"(r[0]), "=r"(r[1]) : "r"(addr));
}

// Stage 1: W[r,i,j] = sum_b comp[r,b] * WF[b,i,j]
__global__ void k_basis(const float* __restrict__ WF, const float* __restrict__ comp) {
    int idx = blockIdx.x * blockDim.x + threadIdx.x;
    if (idx >= RREL * DIN * DOUT) return;
    int r = idx / (DIN * DOUT), ij = idx % (DIN * DOUT);
    float s = 0.f;
#pragma unroll
    for (int b = 0; b < NBASES; ++b)
        s += comp[r * NBASES + b] * WF[b * (DIN * DOUT) + ij];
    g_W[idx] = s;
}

// Stage 2: FW = X @ W_r -> fp16 hi/lo split, transposed [c][k]
__global__ void k_fw(const float* __restrict__ X) {
    __shared__ float Ws[DIN * DOUT];
    __shared__ float Xs[32 * DIN];
    const int r = blockIdx.x, nblk = blockIdx.y, t = threadIdx.x;

    for (int i = t; i < DIN * DOUT; i += 256) Ws[i] = g_W[r * DIN * DOUT + i];
    for (int i = t; i < 32 * DIN;  i += 256) Xs[i] = X[(size_t)(nblk * 32) * DIN + i];
    __syncthreads();

    const int row = t >> 3;
    const int c0  = (t & 7) * 4;
    float a[4] = {0.f, 0.f, 0.f, 0.f};
#pragma unroll
    for (int i = 0; i < DIN; ++i) {
        float x = Xs[row * DIN + i];
        float4 w = *(const float4*)&Ws[i * DOUT + c0];
        a[0] += x * w.x; a[1] += x * w.y; a[2] += x * w.z; a[3] += x * w.w;
    }
    int k = r * NNODES + nblk * 32 + row;
#pragma unroll
    for (int i = 0; i < 4; ++i) {
        __half h = __float2half_rn(a[i]);
        __half l = __float2half_rn(a[i] - __half2float(h));
        g_Bh[(size_t)(c0 + i) * KFULL + k] = h;
        g_Bl[(size_t)(c0 + i) * KFULL + k] = l;
    }
}

// Stage 3: split-K GEMM. Coalesced fp32 LDG -> in-reg fp16 convert ->
// SW128-swizzled smem -> ldmatrix fragments -> 2-product mma.sync (A*(Bh+Bl)).
__global__ __launch_bounds__(256, 2) void k_gemm(const float* __restrict__ A) {
    extern __shared__ char smem[];
    const uint32_t sbase = (uint32_t)__cvta_generic_to_shared(smem);

    const int t    = threadIdx.x;
    const int wid  = t >> 5, lane = t & 31;
    const int m0   = blockIdx.x * M_TILE;
    const size_t kb0 = (size_t)blockIdx.y * KCHUNK;

    // A loader mapping: rows arow0 + 16*i, float4 position apos
    const int arow0 = t >> 4;
    const int apos  = t & 15;
    const float* Asrc = A + (size_t)m0 * KFULL + kb0 + apos * 4;

    // B loader mapping (cp.async, swizzled dst)
    const int bn = t >> 3, bkc = t & 7;
    const uint32_t boff = bn * 128 + ((bkc ^ (bn & 7)) << 4);
    const __half* bsrc_h = g_Bh + (size_t)bn * KFULL + kb0 + bkc * 8;
    const __half* bsrc_l = g_Bl + (size_t)bn * KFULL + kb0 + bkc * 8;

    // ldmatrix per-lane patterns
    const int a_row  = wid * 16 + (lane & 15);
    const int a_csel = lane >> 4;
    const int b_n    = lane & 7;
    const int b_csel = (lane >> 3) & 1;

    // prologue: B(0) cp.async + A(0) regs
    cp_async16(sbase + OFF_BH + boff, bsrc_h);
    cp_async16(sbase + OFF_BL + boff, bsrc_l);
    asm volatile("cp.async.commit_group;");

    float4 areg[8];
#pragma unroll
    for (int i = 0; i < 8; ++i)
        areg[i] = *(const float4*)(Asrc + (size_t)(arow0 + 16 * i) * KFULL);

    float d[4][4] = {};

    for (int step = 0; step < NSTEPS; ++step) {
        const int buf = step & 1;
        const uint32_t sb = sbase + buf * STG_B;

        // convert + STS A(step) into buf
        {
            const int chunk = apos >> 1, half = apos & 1;
#pragma unroll
            for (int i = 0; i < 8; ++i) {
                const int row = arow0 + 16 * i;
                float4 f = areg[i];
                uint32_t h01, h23;
                asm("cvt.rn.f16x2.f32 %0, %1, %2;" : "=r"(h01) : "f"(f.y), "f"(f.x));
                asm("cvt.rn.f16x2.f32 %0, %1, %2;" : "=r"(h23) : "f"(f.w), "f"(f.z));
                const uint32_t off = row * 128 + ((chunk ^ (row & 7)) << 4) + half * 8;
                *(uint2*)(smem + buf * STG_B + OFF_AH + off) = make_uint2(h01, h23);
            }
        }

        // prefetch A(step+1) regs + B(step+1) cp.async into buf^1
        if (step + 1 < NSTEPS) {
            const float* asrc2 = Asrc + (step + 1) * KT;
#pragma unroll
            for (int i = 0; i < 8; ++i)
                areg[i] = *(const float4*)(asrc2 + (size_t)(arow0 + 16 * i) * KFULL);
            const uint32_t nb = sbase + (buf ^ 1) * STG_B;
            cp_async16(nb + OFF_BH + boff, bsrc_h + (step + 1) * KT);
            cp_async16(nb + OFF_BL + boff, bsrc_l + (step + 1) * KT);
            asm volatile("cp.async.commit_group;");
            asm volatile("cp.async.wait_group 1;");
        } else {
            asm volatile("cp.async.wait_group 0;");
        }
        __syncthreads();

        // compute on buf
        const uint32_t ah_base = sb + OFF_AH + a_row * 128;
#pragma unroll
        for (int kt = 0; kt < 4; ++kt) {
            const int achunk = (2 * kt + a_csel) ^ (a_row & 7);
            uint32_t ah[4];
            ldmatrix_x4(ah, ah_base + (achunk << 4));
#pragma unroll
            for (int n = 0; n < 4; ++n) {
                const int nrow = n * 8 + b_n;
                const int bchunk = (2 * kt + b_csel) ^ (nrow & 7);
                uint32_t bh[2], bl[2];
                ldmatrix_x2(bh, sb + OFF_BH + nrow * 128 + (bchunk << 4));
                ldmatrix_x2(bl, sb + OFF_BL + nrow * 128 + (bchunk << 4));
                mma16816(d[n], ah, bh[0], bh[1]);
                mma16816(d[n], ah, bl[0], bl[1]);
            }
        }
        __syncthreads();
    }

    // epilogue: rows wid*16 + lane/4 (+8), cols n*8 + (lane%4)*2
    const int r4 = lane >> 2, kq = (lane & 3) * 2;
    float* po = g_part + ((size_t)blockIdx.y * NNODES + m0 + wid * 16 + r4) * DOUT + kq;
#pragma unroll
    for (int n = 0; n < 4; ++n) {
        *(float2*)(po + n * 8)            = make_float2(d[n][0], d[n][1]);
        *(float2*)(po + 8 * DOUT + n * 8) = make_float2(d[n][2], d[n][3]);
    }
}

// Stage 4: deterministic split-K reduction (float2 granularity for parallelism)
__global__ void k_reduce(float* __restrict__ out) {
    int i = blockIdx.x * blockDim.x + threadIdx.x;   // over 65536 float2s
    const float2* p = (const float2*)g_part;
    float2 s = p[i];
#pragma unroll
    for (int sdx = 1; sdx < KSPLIT; ++sdx) {
        float2 v = p[(size_t)sdx * (NNODES * DOUT / 2) + i];
        s.x += v.x; s.y += v.y;
    }
    ((float2*)out)[i] = s;
}

extern "C" void kernel_launch(void* const* d_in, const int* in_sizes, int n_in,
                              void* d_out, int out_size) {
    const float* X    = (const float*)d_in[0];   // [4096, 64]
    const float* A    = (const float*)d_in[1];   // [4096, 65536]
    const float* WF   = (const float*)d_in[2];   // [8, 64, 32]
    const float* comp = (const float*)d_in[3];   // [16, 8]
    float* out = (float*)d_out;                  // [4096, 32]

    cudaFuncSetAttribute((const void*)k_gemm,
                         cudaFuncAttributeMaxDynamicSharedMemorySize, SMEM_BYTES);

    k_basis<<<(RREL * DIN * DOUT + 255) / 256, 256>>>(WF, comp);
    k_fw<<<dim3(RREL, NNODES / 32), 256>>>(X);
    k_gemm<<<dim3(NNODES / M_TILE, KSPLIT), 256, SMEM_BYTES>>>(A);
    k_reduce<<<(NNODES * DOUT / 2) / 256, 256>>>(out);
}

// round 8
// speedup vs baseline: 1.1238x; 1.1238x over previous
#include <cuda_runtime.h>
#include <cuda_fp16.h>
#include <cstdint>

#define NNODES 4096
#define RREL   16
#define NBASES 8
#define DIN    64
#define DOUT   32
#define KFULL  (RREL * NNODES)          // 65536

#define M_TILE 128
#define KT     64                       // k per step (4 mma k-tiles of 16)
#define KSPLIT 64
#define KCHUNK (KFULL / KSPLIT)         // 1024
#define NSTEPS (KCHUNK / KT)            // 16

// per-stage smem layout (bytes): A 16K | B-hi 4K | B-lo 4K
#define OFF_AH 0
#define OFF_BH 16384
#define OFF_BL 20480
#define STG_B  24576
#define SMEM_BYTES (2 * STG_B)          // 48 KB dynamic

__device__ float g_W[RREL * DIN * DOUT];
__device__ __half g_Bh[(size_t)DOUT * KFULL];            // [c][k], 4 MB
__device__ __half g_Bl[(size_t)DOUT * KFULL];            // 4 MB
__device__ float g_part[(size_t)KSPLIT * NNODES * DOUT]; // 32 MB

__device__ __forceinline__ void mma16816(float* d, const uint32_t* a,
                                         uint32_t b0, uint32_t b1) {
    asm volatile(
        "mma.sync.aligned.m16n8k16.row.col.f32.f16.f16.f32 "
        "{%0,%1,%2,%3}, {%4,%5,%6,%7}, {%8,%9}, {%0,%1,%2,%3};"
        : "+f"(d[0]), "+f"(d[1]), "+f"(d[2]), "+f"(d[3])
        : "r"(a[0]), "r"(a[1]), "r"(a[2]), "r"(a[3]), "r"(b0), "r"(b1));
}
__device__ __forceinline__ void cp_async16(uint32_t saddr, const void* g) {
    asm volatile("cp.async.cg.shared.global [%0], [%1], 16;" :: "r"(saddr), "l"(g));
}
__device__ __forceinline__ void ldmatrix_x4(uint32_t* r, uint32_t addr) {
    asm volatile("ldmatrix.sync.aligned.m8n8.x4.shared.b16 {%0,%1,%2,%3}, [%4];"
                 : "=r"(r[0]), "=r"(r[1]), "=r"(r[2]), "=r"(r[3]) : "r"(addr));
}
__device__ __forceinline__ void ldmatrix_x2(uint32_t* r, uint32_t addr) {
    asm volatile("ldmatrix.sync.aligned.m8n8.x2.shared.b16 {%0,%1}, [%2];"
                 : "=r"(r[0]), "=r"(r[1]) : "r"(addr));
}
// evict-first streaming load of a float4 (A is single-use; keep B hot in L2)
__device__ __forceinline__ float4 ldcs4(const float* p) {
    float4 v;
    asm volatile("ld.global.cs.v4.f32 {%0,%1,%2,%3}, [%4];"
                 : "=f"(v.x), "=f"(v.y), "=f"(v.z), "=f"(v.w) : "l"(p));
    return v;
}

// Stage 1: W[r,i,j] = sum_b comp[r,b] * WF[b,i,j]
__global__ void k_basis(const float* __restrict__ WF, const float* __restrict__ comp) {
    int idx = blockIdx.x * blockDim.x + threadIdx.x;
    if (idx >= RREL * DIN * DOUT) return;
    int r = idx / (DIN * DOUT), ij = idx % (DIN * DOUT);
    float s = 0.f;
#pragma unroll
    for (int b = 0; b < NBASES; ++b)
        s += comp[r * NBASES + b] * WF[b * (DIN * DOUT) + ij];
    g_W[idx] = s;
}

// Stage 2: FW = X @ W_r -> fp16 hi/lo split, transposed [c][k]
__global__ void k_fw(const float* __restrict__ X) {
    __shared__ float Ws[DIN * DOUT];
    __shared__ float Xs[32 * DIN];
    const int r = blockIdx.x, nblk = blockIdx.y, t = threadIdx.x;

    for (int i = t; i < DIN * DOUT; i += 256) Ws[i] = g_W[r * DIN * DOUT + i];
    for (int i = t; i < 32 * DIN;  i += 256) Xs[i] = X[(size_t)(nblk * 32) * DIN + i];
    __syncthreads();

    const int row = t >> 3;
    const int c0  = (t & 7) * 4;
    float a[4] = {0.f, 0.f, 0.f, 0.f};
#pragma unroll
    for (int i = 0; i < DIN; ++i) {
        float x = Xs[row * DIN + i];
        float4 w = *(const float4*)&Ws[i * DOUT + c0];
        a[0] += x * w.x; a[1] += x * w.y; a[2] += x * w.z; a[3] += x * w.w;
    }
    int k = r * NNODES + nblk * 32 + row;
#pragma unroll
    for (int i = 0; i < 4; ++i) {
        __half h = __float2half_rn(a[i]);
        __half l = __float2half_rn(a[i] - __half2float(h));
        g_Bh[(size_t)(c0 + i) * KFULL + k] = h;
        g_Bl[(size_t)(c0 + i) * KFULL + k] = l;
    }
}

// Stage 3: split-K GEMM. Streaming fp32 LDG.cs -> in-reg fp16 convert ->
// SW128-swizzled smem -> ldmatrix fragments -> 2-product mma.sync (A*(Bh+Bl)).
__global__ __launch_bounds__(256, 2) void k_gemm(const float* __restrict__ A) {
    extern __shared__ char smem[];
    const uint32_t sbase = (uint32_t)__cvta_generic_to_shared(smem);

    const int t    = threadIdx.x;
    const int wid  = t >> 5, lane = t & 31;
    const int m0   = blockIdx.x * M_TILE;
    const size_t kb0 = (size_t)blockIdx.y * KCHUNK;

    // A loader mapping: rows arow0 + 16*i, float4 position apos
    const int arow0 = t >> 4;
    const int apos  = t & 15;
    const float* Asrc = A + (size_t)m0 * KFULL + kb0 + apos * 4;

    // B loader mapping (cp.async, swizzled dst)
    const int bn = t >> 3, bkc = t & 7;
    const uint32_t boff = bn * 128 + ((bkc ^ (bn & 7)) << 4);
    const __half* bsrc_h = g_Bh + (size_t)bn * KFULL + kb0 + bkc * 8;
    const __half* bsrc_l = g_Bl + (size_t)bn * KFULL + kb0 + bkc * 8;

    // ldmatrix per-lane patterns
    const int a_row  = wid * 16 + (lane & 15);
    const int a_csel = lane >> 4;
    const int b_n    = lane & 7;
    const int b_csel = (lane >> 3) & 1;

    // prologue: B(0) cp.async + A(0) regs
    cp_async16(sbase + OFF_BH + boff, bsrc_h);
    cp_async16(sbase + OFF_BL + boff, bsrc_l);
    asm volatile("cp.async.commit_group;");

    float4 areg[8];
#pragma unroll
    for (int i = 0; i < 8; ++i)
        areg[i] = ldcs4(Asrc + (size_t)(arow0 + 16 * i) * KFULL);

    float d[4][4] = {};

    for (int step = 0; step < NSTEPS; ++step) {
        const int buf = step & 1;
        const uint32_t sb = sbase + buf * STG_B;

        // convert + STS A(step) into buf
        {
            const int chunk = apos >> 1, half = apos & 1;
#pragma unroll
            for (int i = 0; i < 8; ++i) {
                const int row = arow0 + 16 * i;
                float4 f = areg[i];
                uint32_t h01, h23;
                asm("cvt.rn.f16x2.f32 %0, %1, %2;" : "=r"(h01) : "f"(f.y), "f"(f.x));
                asm("cvt.rn.f16x2.f32 %0, %1, %2;" : "=r"(h23) : "f"(f.w), "f"(f.z));
                const uint32_t off = row * 128 + ((chunk ^ (row & 7)) << 4) + half * 8;
                *(uint2*)(smem + buf * STG_B + OFF_AH + off) = make_uint2(h01, h23);
            }
        }

        // prefetch A(step+1) regs + B(step+1) cp.async into buf^1
        if (step + 1 < NSTEPS) {
            const float* asrc2 = Asrc + (step + 1) * KT;
#pragma unroll
            for (int i = 0; i < 8; ++i)
                areg[i] = ldcs4(asrc2 + (size_t)(arow0 + 16 * i) * KFULL);
            const uint32_t nb = sbase + (buf ^ 1) * STG_B;
            cp_async16(nb + OFF_BH + boff, bsrc_h + (step + 1) * KT);
            cp_async16(nb + OFF_BL + boff, bsrc_l + (step + 1) * KT);
            asm volatile("cp.async.commit_group;");
            asm volatile("cp.async.wait_group 1;");
        } else {
            asm volatile("cp.async.wait_group 0;");
        }
        __syncthreads();

        // compute on buf
        const uint32_t ah_base = sb + OFF_AH + a_row * 128;
#pragma unroll
        for (int kt = 0; kt < 4; ++kt) {
            const int achunk = (2 * kt + a_csel) ^ (a_row & 7);
            uint32_t ah[4];
            ldmatrix_x4(ah, ah_base + (achunk << 4));
#pragma unroll
            for (int n = 0; n < 4; ++n) {
                const int nrow = n * 8 + b_n;
                const int bchunk = (2 * kt + b_csel) ^ (nrow & 7);
                uint32_t bh[2], bl[2];
                ldmatrix_x2(bh, sb + OFF_BH + nrow * 128 + (bchunk << 4));
                ldmatrix_x2(bl, sb + OFF_BL + nrow * 128 + (bchunk << 4));
                mma16816(d[n], ah, bh[0], bh[1]);
                mma16816(d[n], ah, bl[0], bl[1]);
            }
        }
        __syncthreads();
    }

    // epilogue: rows wid*16 + lane/4 (+8), cols n*8 + (lane%4)*2
    const int r4 = lane >> 2, kq = (lane & 3) * 2;
    float* po = g_part + ((size_t)blockIdx.y * NNODES + m0 + wid * 16 + r4) * DOUT + kq;
#pragma unroll
    for (int n = 0; n < 4; ++n) {
        *(float2*)(po + n * 8)            = make_float2(d[n][0], d[n][1]);
        *(float2*)(po + 8 * DOUT + n * 8) = make_float2(d[n][2], d[n][3]);
    }
}

// Stage 4: deterministic split-K reduction (float2 granularity)
__global__ void k_reduce(float* __restrict__ out) {
    int i = blockIdx.x * blockDim.x + threadIdx.x;   // over 65536 float2s
    const float2* p = (const float2*)g_part;
    float2 s = p[i];
#pragma unroll
    for (int sdx = 1; sdx < KSPLIT; ++sdx) {
        float2 v = p[(size_t)sdx * (NNODES * DOUT / 2) + i];
        s.x += v.x; s.y += v.y;
    }
    ((float2*)out)[i] = s;
}

extern "C" void kernel_launch(void* const* d_in, const int* in_sizes, int n_in,
                              void* d_out, int out_size) {
    const float* X    = (const float*)d_in[0];   // [4096, 64]
    const float* A    = (const float*)d_in[1];   // [4096, 65536]
    const float* WF   = (const float*)d_in[2];   // [8, 64, 32]
    const float* comp = (const float*)d_in[3];   // [16, 8]
    float* out = (float*)d_out;                  // [4096, 32]

    cudaFuncSetAttribute((const void*)k_gemm,
                         cudaFuncAttributeMaxDynamicSharedMemorySize, SMEM_BYTES);

    k_basis<<<(RREL * DIN * DOUT + 255) / 256, 256>>>(WF, comp);
    k_fw<<<dim3(RREL, NNODES / 32), 256>>>(X);
    k_gemm<<<dim3(NNODES / M_TILE, KSPLIT), 256, SMEM_BYTES>>>(A);
    k_reduce<<<(NNODES * DOUT / 2) / 256, 256>>>(out);
}